// round 12
// baseline (speedup 1.0000x reference)
#include <cuda_runtime.h>
#include <cstdint>

#define N_NODES 50000
#define D 128
#define BIN_CAP 192
#define WPAD 132
#define NPB 64            // nodes per block

// Scratch (allocation-free: __device__ globals)
__device__ int g_deg[N_NODES];                       // in-degree / fill cursor
__device__ int g_bin[(size_t)N_NODES * BIN_CAP];     // edge ids binned by dst (38.4 MB)

// ---------------------------------------------------------------------------
// Kernel 1: zero the degree counters (tiny: 200 KB)
// ---------------------------------------------------------------------------
__global__ void zero_deg_kernel() {
    int i = blockIdx.x * blockDim.x + threadIdx.x;
    if (i < N_NODES) g_deg[i] = 0;
}

// ---------------------------------------------------------------------------
// Kernel 2: bin edges by destination. One thread per edge.
// ---------------------------------------------------------------------------
__global__ void fill_kernel(const int* __restrict__ dst, int E) {
    int e = blockIdx.x * blockDim.x + threadIdx.x;
    if (e >= E) return;
    int d = __ldg(&dst[e]);
    int pos = atomicAdd(&g_deg[d], 1);
    if (pos < BIN_CAP) g_bin[(size_t)d * BIN_CAP + pos] = e;
}

// ---------------------------------------------------------------------------
// Kernel 3: FUSED aggregate + GEMM. Block = 256 threads = 8 warps, 64 nodes.
//  Phase A: stage W[128][128] into padded smem.
//  Phase B: warp w gathers+means nodes (base + w*8 .. +7) into smem ft rows
//           (same measured gather loop as r10/r11; ft never touches DRAM).
//  Phase C: 64x128 GEMM vs W^T, 4x8 thread tile (32 acc, ~100 regs,
//           2 CTAs/SM -> 16 warps/SM; gather CTAs overlap GEMM CTAs).
// ---------------------------------------------------------------------------
__global__ void __launch_bounds__(256, 2) fused_kernel(const int* __restrict__ src,
                                                       const float* __restrict__ h,
                                                       const float* __restrict__ r,
                                                       const float* __restrict__ W,
                                                       const float* __restrict__ b,
                                                       float* __restrict__ out) {
    extern __shared__ float smem[];
    float* Ws  = smem;                   // [128][WPAD]
    float* ftb = smem + 128 * WPAD;      // [NPB][WPAD]

    const int tid  = threadIdx.x;
    const int wid  = tid >> 5;
    const int lane = tid & 31;
    const int base = blockIdx.x * NPB;

    // --- Phase A: stage W (coalesced float4; 528B row stride) ---
    for (int idx = tid * 4; idx < 128 * 128; idx += 256 * 4) {
        int row = idx >> 7;
        int col = idx & 127;
        float4 v = *reinterpret_cast<const float4*>(W + row * 128 + col);
        *reinterpret_cast<float4*>(Ws + row * WPAD + col) = v;
    }

    // --- Phase B: gather + mean, one warp per node, 8 nodes per warp ---
    const float4* __restrict__ h4 = reinterpret_cast<const float4*>(h);
    const float4* __restrict__ r4 = reinterpret_cast<const float4*>(r);

    for (int t = 0; t < 8; t++) {
        const int rr = wid * 8 + t;          // local row 0..63
        const int n  = base + rr;
        float4 acc = make_float4(0.f, 0.f, 0.f, 0.f);
        if (n < N_NODES) {
            const int deg = g_deg[n];
            const int m = min(deg, BIN_CAP);
            for (int bb = 0; bb < m; bb += 32) {
                const int cnt = min(32, m - bb);
                int eid = 0, sv = 0;
                if (lane < cnt) {
                    eid = g_bin[(size_t)n * BIN_CAP + bb + lane];
                    sv  = __ldg(&src[eid]);
                }
#pragma unroll 4
                for (int j = 0; j < cnt; j++) {
                    int e = __shfl_sync(0xffffffffu, eid, j);
                    int s = __shfl_sync(0xffffffffu, sv, j);
                    float4 hv = h4[(size_t)s * 32 + lane];
                    float4 rv = r4[(size_t)e * 32 + lane];
                    acc.x += hv.x + rv.x;
                    acc.y += hv.y + rv.y;
                    acc.z += hv.z + rv.z;
                    acc.w += hv.w + rv.w;
                }
            }
            const float inv = 1.0f / fmaxf((float)deg, 1.0f);
            acc.x *= inv; acc.y *= inv; acc.z *= inv; acc.w *= inv;
        }
        *reinterpret_cast<float4*>(ftb + rr * WPAD + lane * 4) = acc;
    }
    __syncthreads();

    // --- Phase C: 64x128 GEMM. Thread tile 4 rows x 8 cols. ---
    const int cg = tid & 15;     // cols j = cg + 16*m
    const int rg = tid >> 4;     // rows rr = rg*4 + i   (rg 0..15)

    float acc2[4][8];
#pragma unroll
    for (int i = 0; i < 4; i++)
#pragma unroll
        for (int m = 0; m < 8; m++) acc2[i][m] = 0.f;

    for (int k = 0; k < 128; k += 4) {
        float4 fv[4];
        float4 wv[8];
#pragma unroll
        for (int i = 0; i < 4; i++)
            fv[i] = *reinterpret_cast<const float4*>(ftb + (rg * 4 + i) * WPAD + k);
#pragma unroll
        for (int m = 0; m < 8; m++)
            wv[m] = *reinterpret_cast<const float4*>(Ws + (cg + 16 * m) * WPAD + k);
#pragma unroll
        for (int i = 0; i < 4; i++)
#pragma unroll
            for (int m = 0; m < 8; m++)
                acc2[i][m] += fv[i].x * wv[m].x + fv[i].y * wv[m].y +
                              fv[i].z * wv[m].z + fv[i].w * wv[m].w;
    }

    float bj[8];
#pragma unroll
    for (int m = 0; m < 8; m++) bj[m] = __ldg(&b[cg + 16 * m]);

#pragma unroll
    for (int i = 0; i < 4; i++) {
        const int n = base + rg * 4 + i;
        if (n < N_NODES) {
#pragma unroll
            for (int m = 0; m < 8; m++)
                out[(size_t)n * D + cg + 16 * m] = acc2[i][m] + bj[m];
        }
    }
}

// ---------------------------------------------------------------------------
// Launcher
// ---------------------------------------------------------------------------
extern "C" void kernel_launch(void* const* d_in, const int* in_sizes, int n_in,
                              void* d_out, int out_size) {
    const int*   src = (const int*)d_in[0];
    const int*   dst = (const int*)d_in[1];
    const float* h   = (const float*)d_in[2];
    const float* r   = (const float*)d_in[3];
    const float* W   = (const float*)d_in[4];
    const float* b   = (const float*)d_in[5];
    float* out = (float*)d_out;

    const int E = in_sizes[0];

    const size_t smem_bytes = (size_t)(128 + NPB) * WPAD * sizeof(float);  // 101376 B

    static bool attr_done = false;
    if (!attr_done) {
        cudaFuncSetAttribute(fused_kernel,
                             cudaFuncAttributeMaxDynamicSharedMemorySize,
                             (int)smem_bytes);
        attr_done = true;
    }

    // 1) zero degree counters
    zero_deg_kernel<<<(N_NODES + 255) / 256, 256>>>();

    // 2) bin edges by dst
    fill_kernel<<<(E + 255) / 256, 256>>>(dst, E);

    // 3) fused gather + mean + GEMM
    {
        int blocks = (N_NODES + NPB - 1) / NPB;   // 782
        fused_kernel<<<blocks, 256, smem_bytes>>>(src, h, r, W, b, out);
    }
}

// round 13
// speedup vs baseline: 1.4311x; 1.4311x over previous
#include <cuda_runtime.h>
#include <cstdint>

#define N_NODES 50000
#define D 128
#define BIN_CAP 192
#define WPAD 132

// Scratch (allocation-free: __device__ globals)
__device__ int   g_deg[N_NODES];                         // in-degree / fill cursor
__device__ int   g_bin[(size_t)N_NODES * BIN_CAP];       // edge ids binned by dst (38.4 MB)
__device__ float g_ft[(size_t)N_NODES * D];              // mean-aggregated features (25.6 MB)

// ---------------------------------------------------------------------------
// Kernel 1: zero the degree counters (tiny: 200 KB)
// ---------------------------------------------------------------------------
__global__ void zero_deg_kernel() {
    int i = blockIdx.x * blockDim.x + threadIdx.x;
    if (i < N_NODES) g_deg[i] = 0;
}

// ---------------------------------------------------------------------------
// Kernel 2: bin edges by destination. One thread per edge.
// ---------------------------------------------------------------------------
__global__ void fill_kernel(const int* __restrict__ dst, int E) {
    int e = blockIdx.x * blockDim.x + threadIdx.x;
    if (e >= E) return;
    int d = __ldg(&dst[e]);
    int pos = atomicAdd(&g_deg[d], 1);
    if (pos < BIN_CAP) g_bin[(size_t)d * BIN_CAP + pos] = e;
}

// ---------------------------------------------------------------------------
// Kernel 3: per-node aggregation. One warp per node, register accumulation,
// single write of the mean. UNCHANGED from the measured 290.9us baseline —
// it is latency-bound and needs its high occupancy (r12 fusion proved this).
// ---------------------------------------------------------------------------
__global__ void __launch_bounds__(256) aggregate_kernel(const int* __restrict__ src,
                                                        const float* __restrict__ h,
                                                        const float* __restrict__ r) {
    int gwarp = (blockIdx.x * blockDim.x + threadIdx.x) >> 5;
    int lane  = threadIdx.x & 31;
    if (gwarp >= N_NODES) return;
    const int n = gwarp;

    const int deg = g_deg[n];
    const int m = min(deg, BIN_CAP);

    const float4* __restrict__ h4 = reinterpret_cast<const float4*>(h);
    const float4* __restrict__ r4 = reinterpret_cast<const float4*>(r);

    float4 acc = make_float4(0.f, 0.f, 0.f, 0.f);

    for (int base = 0; base < m; base += 32) {
        const int cnt = min(32, m - base);
        int eid = 0, sv = 0;
        if (lane < cnt) {
            eid = g_bin[(size_t)n * BIN_CAP + base + lane];
            sv  = __ldg(&src[eid]);
        }
#pragma unroll 4
        for (int j = 0; j < cnt; j++) {
            int e = __shfl_sync(0xffffffffu, eid, j);
            int s = __shfl_sync(0xffffffffu, sv, j);
            float4 hv = h4[(size_t)s * 32 + lane];
            float4 rv = r4[(size_t)e * 32 + lane];
            acc.x += hv.x + rv.x;
            acc.y += hv.y + rv.y;
            acc.z += hv.z + rv.z;
            acc.w += hv.w + rv.w;
        }
    }

    const float inv = 1.0f / fmaxf((float)deg, 1.0f);
    acc.x *= inv; acc.y *= inv; acc.z *= inv; acc.w *= inv;
    reinterpret_cast<float4*>(g_ft)[(size_t)n * 32 + lane] = acc;
}

// ---------------------------------------------------------------------------
// Kernel 4: 2D register-tiled GEMM, occupancy-sized.
// Block = 256 threads, tile = 64 rows x 128 cols, thread tile = 4x8
// (32 accs, ~100 regs). smem = (128+64)*WPAD*4 = 101 KB -> 2 CTAs/SM
// = 16 warps/SM (2x r11). Per 4-k chunk: 12 LDS.128 per 128 FMAs.
// ---------------------------------------------------------------------------
#define GTILE_ROWS 64

__global__ void __launch_bounds__(256, 2) gemm_kernel(const float* __restrict__ W,
                                                      const float* __restrict__ b,
                                                      float* __restrict__ out) {
    extern __shared__ float smem[];
    float* Ws  = smem;                       // [128][WPAD] j-major
    float* ftb = smem + 128 * WPAD;          // [64][WPAD]  row-major

    const int tid = threadIdx.x;
    const int row_base = blockIdx.x * GTILE_ROWS;

    // Stage W [128][128] into padded smem (coalesced float4).
    for (int idx = tid * 4; idx < 128 * 128; idx += 256 * 4) {
        int row = idx >> 7;
        int col = idx & 127;
        float4 v = *reinterpret_cast<const float4*>(W + row * 128 + col);
        *reinterpret_cast<float4*>(Ws + row * WPAD + col) = v;
    }

    // Stage 64 ft rows.
    for (int idx = tid * 4; idx < GTILE_ROWS * 128; idx += 256 * 4) {
        int rr  = idx >> 7;
        int col = idx & 127;
        int n   = row_base + rr;
        float4 v = make_float4(0.f, 0.f, 0.f, 0.f);
        if (n < N_NODES)
            v = *reinterpret_cast<const float4*>(g_ft + (size_t)n * D + col);
        *reinterpret_cast<float4*>(ftb + rr * WPAD + col) = v;
    }
    __syncthreads();

    const int cg = tid & 15;     // cols j = cg + 16*m
    const int rg = tid >> 4;     // rows rr = rg*4 + i   (rg 0..15)

    float acc[4][8];
#pragma unroll
    for (int i = 0; i < 4; i++)
#pragma unroll
        for (int m = 0; m < 8; m++) acc[i][m] = 0.f;

    for (int k = 0; k < 128; k += 4) {
        float4 fv[4];
        float4 wv[8];
#pragma unroll
        for (int i = 0; i < 4; i++)
            fv[i] = *reinterpret_cast<const float4*>(ftb + (rg * 4 + i) * WPAD + k);
#pragma unroll
        for (int m = 0; m < 8; m++)
            wv[m] = *reinterpret_cast<const float4*>(Ws + (cg + 16 * m) * WPAD + k);
#pragma unroll
        for (int i = 0; i < 4; i++)
#pragma unroll
            for (int m = 0; m < 8; m++)
                acc[i][m] += fv[i].x * wv[m].x + fv[i].y * wv[m].y +
                             fv[i].z * wv[m].z + fv[i].w * wv[m].w;
    }

    float bj[8];
#pragma unroll
    for (int m = 0; m < 8; m++) bj[m] = __ldg(&b[cg + 16 * m]);

#pragma unroll
    for (int i = 0; i < 4; i++) {
        const int n = row_base + rg * 4 + i;
        if (n < N_NODES) {
#pragma unroll
            for (int m = 0; m < 8; m++)
                out[(size_t)n * D + cg + 16 * m] = acc[i][m] + bj[m];
        }
    }
}

// ---------------------------------------------------------------------------
// Launcher
// ---------------------------------------------------------------------------
extern "C" void kernel_launch(void* const* d_in, const int* in_sizes, int n_in,
                              void* d_out, int out_size) {
    const int*   src = (const int*)d_in[0];
    const int*   dst = (const int*)d_in[1];
    const float* h   = (const float*)d_in[2];
    const float* r   = (const float*)d_in[3];
    const float* W   = (const float*)d_in[4];
    const float* b   = (const float*)d_in[5];
    float* out = (float*)d_out;

    const int E = in_sizes[0];

    const size_t smem_bytes = (size_t)(128 + GTILE_ROWS) * WPAD * sizeof(float);  // 101376 B

    static bool attr_done = false;
    if (!attr_done) {
        cudaFuncSetAttribute(gemm_kernel,
                             cudaFuncAttributeMaxDynamicSharedMemorySize,
                             (int)smem_bytes);
        attr_done = true;
    }

    // 1) zero degree counters
    zero_deg_kernel<<<(N_NODES + 255) / 256, 256>>>();

    // 2) bin edges by dst
    fill_kernel<<<(E + 255) / 256, 256>>>(dst, E);

    // 3) per-node mean aggregation (one warp per node, high occupancy)
    {
        int total_threads = N_NODES * 32;
        aggregate_kernel<<<(total_threads + 255) / 256, 256>>>(src, h, r);
    }

    // 4) occupancy-sized 2D register-tiled GEMM
    {
        int blocks = (N_NODES + GTILE_ROWS - 1) / GTILE_ROWS;  // 782
        gemm_kernel<<<blocks, 256, smem_bytes>>>(W, b, out);
    }
}